// round 7
// baseline (speedup 1.0000x reference)
#include <cuda_runtime.h>
#include <cuda_bf16.h>
#include <cstdint>

// ---------------------------------------------------------------------------
// MatchingNetwork — Round 7: split-int8 IMMA GEMM, M-tile 64, 128-thread CTAs
// (3-4 CTAs/SM), early quantize (low reg staging), double-buffered.
// ---------------------------------------------------------------------------

#define B_SZ   256
#define S_SZ   20
#define V_SZ   20000
#define C_SZ   20
#define D_SZ   64
#define M_SUP  (B_SZ * S_SZ)      // 5120
#define M_ALL  (M_SUP + B_SZ)     // 5376
#define KSPLIT 7
#define NIT    45                 // 64-elem chunks per k-slice

#define PITCH  80u                // smem row pitch (64B data + 16B pad)
#define OF_AL  5120u              // 64*80
#define OF_BH  10240u
#define OF_BL  15360u
#define BUFSZ  20480u
#define SMEM_TOTAL 40960

// scale: qa = round(x*32512); qw = round(w*32512/0.04)
#define KSC    (0.04f / (32512.f * 32512.f))
#define K1SC   (65536.f * KSC)
#define K2SC   (256.f * KSC)

typedef uint32_t u32;

// ---- device scratch ---------------------------------------------------------
__device__ float g_part[(size_t)KSPLIT * M_ALL * D_SZ];
__device__ float g_sup[(size_t)M_ALL * D_SZ];
__device__ u32   g_qwh[(size_t)D_SZ * (V_SZ / 4)];
__device__ u32   g_qwl[(size_t)D_SZ * (V_SZ / 4)];
__device__ float g_pb[2 * B_SZ];

// ---- PTX helpers ------------------------------------------------------------
__device__ __forceinline__ u32 smem_u32(const void* p) {
    u32 a;
    asm("{ .reg .u64 t; cvta.to.shared.u64 t, %1; cvt.u32.u64 %0, t; }"
        : "=r"(a) : "l"(p));
    return a;
}
__device__ __forceinline__ void sts32(u32 a, u32 v) {
    asm volatile("st.shared.b32 [%0], %1;" :: "r"(a), "r"(v));
}
__device__ __forceinline__ void cp16(u32 s, const void* g) {
    asm volatile("cp.async.cg.shared.global [%0], [%1], 16;" :: "r"(s), "l"(g));
}
#define CP_COMMIT() asm volatile("cp.async.commit_group;" ::: "memory")
#define CP_WAIT0()  asm volatile("cp.async.wait_group 0;" ::: "memory")

__device__ __forceinline__ void ldm4(u32 a, u32 r[4]) {
    asm volatile("ldmatrix.sync.aligned.m8n8.x4.shared.b16 {%0,%1,%2,%3}, [%4];"
        : "=r"(r[0]), "=r"(r[1]), "=r"(r[2]), "=r"(r[3]) : "r"(a));
}
__device__ __forceinline__ void imma(int c[4], const u32 a[4], const u32* b) {
    asm volatile("mma.sync.aligned.m16n8k32.row.col.s32.s8.s8.s32 "
        "{%0,%1,%2,%3}, {%4,%5,%6,%7}, {%8,%9}, {%0,%1,%2,%3};"
        : "+r"(c[0]), "+r"(c[1]), "+r"(c[2]), "+r"(c[3])
        : "r"(a[0]), "r"(a[1]), "r"(a[2]), "r"(a[3]), "r"(b[0]), "r"(b[1]));
}
// convert float4 -> packed (ah, al) bytes
__device__ __forceinline__ void quant4(float4 v, u32& ahp, u32& alp) {
    u32 b0 = __float_as_uint(fmaf(v.x, 32512.f, 12583040.f));
    u32 b1 = __float_as_uint(fmaf(v.y, 32512.f, 12583040.f));
    u32 b2 = __float_as_uint(fmaf(v.z, 32512.f, 12583040.f));
    u32 b3 = __float_as_uint(fmaf(v.w, 32512.f, 12583040.f));
    u32 c01 = __byte_perm(b0, b1, 0x5410);
    u32 c23 = __byte_perm(b2, b3, 0x5410);
    ahp = __byte_perm(c01, c23, 0x7531);
    alp = __byte_perm(c01, c23, 0x6420) ^ 0x80808080u;
}

// ---- K0: quantize W -> (wh, wl) int8 pairs, fixed scale ----------------------
__global__ void prep_w_kernel(const float* __restrict__ W) {
    int idx = blockIdx.x * 256 + threadIdx.x;    // covers 64*5000 u32 exactly
    float4 v = *reinterpret_cast<const float4*>(W + (size_t)idx * 4);
    int qw[4], wh[4], wl[4];
    float f[4] = {v.x, v.y, v.z, v.w};
    #pragma unroll
    for (int i = 0; i < 4; ++i) {
        float t = fminf(fmaxf(f[i] * 812800.f, -32512.f), 32512.f);
        qw[i] = __float2int_rn(t);
        wh[i] = (qw[i] + 128) >> 8;              // [-127,127]
        wl[i] = qw[i] - (wh[i] << 8);            // [-128,127]
    }
    u32 hp = (u32)(wh[0] & 255) | ((u32)(wh[1] & 255) << 8)
           | ((u32)(wh[2] & 255) << 16) | ((u32)(wh[3] & 255) << 24);
    u32 lp = (u32)(wl[0] & 255) | ((u32)(wl[1] & 255) << 8)
           | ((u32)(wl[2] & 255) << 16) | ((u32)(wl[3] & 255) << 24);
    g_qwh[idx] = hp;
    g_qwl[idx] = lp;
}

// ---- K1: split-int8 IMMA GEMM, M-tile 64, 128 threads --------------------------
// grid = (84 m-tiles, 7 k-slices), 4 warps in 2x2, warp tile m32 x n32
__global__ __launch_bounds__(128) void gemm_kernel(
    const float* __restrict__ img, const float* __restrict__ tgtim)
{
    extern __shared__ char smem[];
    const u32 sb = smem_u32(smem);
    const int tid  = threadIdx.x;
    const int w    = tid >> 5;
    const int lane = tid & 31;
    const int wm   = w >> 1;             // m half
    const int wn   = w & 1;              // n half
    const int row0 = blockIdx.x * 64;
    const int ks   = blockIdx.y;

    // k-slice in 32-elem units: 625 total -> 90,90,89,89,89,89,89
    const int ubeg = ks * 89 + (ks < 2 ? ks : 2);
    const int ucnt = 89 + (ks < 2 ? 1 : 0);

    const float* abase = (blockIdx.x < 80)
        ? img   + (size_t)row0 * V_SZ
        : tgtim + (size_t)(row0 - M_SUP) * V_SZ;

    // A fill (coalesced): 16 lanes per row; 8 rows per pass, 8 passes = 64 rows
    const int arow0 = tid >> 4;          // 0..7
    const int c16   = tid & 15;          // float4 index within 64-float chunk
    // B fill: 2 threads per row (64 rows), 2 x 16B pieces each per array
    const int brow = tid >> 1, bp0 = (tid & 1) * 2;
    const char* gwh = (const char*)g_qwh + (size_t)brow * V_SZ;
    const char* gwl = (const char*)g_qwl + (size_t)brow * V_SZ;

    // ldmatrix lane bases
    const u32 aLB = (u32)(wm * 32 + (lane & 15)) * PITCH + (u32)((lane >> 4) * 16);
    const u32 bLB = (u32)(wn * 32 + (lane & 7) + ((lane >> 4) & 1) * 8) * PITCH
                  + (u32)(((lane >> 3) & 1) * 16);

    int acc1[2][4][4], acc2[2][4][4];
    #pragma unroll
    for (int mt = 0; mt < 2; ++mt)
        #pragma unroll
        for (int nt = 0; nt < 4; ++nt)
            #pragma unroll
            for (int i = 0; i < 4; ++i) { acc1[mt][nt][i] = 0; acc2[mt][nt][i] = 0; }

    u32 qh[8], ql[8];                    // packed staging (16 regs)
    const u32 sAoff = (u32)arow0 * PITCH + (u32)c16 * 4;

    // ---------- prologue: fill buffer 0 (chunk 0, ns=2) ----------
    {
        const int k0 = ubeg * 32;
        const float* ap = abase + k0 + c16 * 4;
        #pragma unroll
        for (int j = 0; j < 8; ++j) {
            float4 v = *reinterpret_cast<const float4*>(ap + (size_t)(arow0 + 8 * j) * V_SZ);
            quant4(v, qh[j], ql[j]);
        }
        const u32 sB = sb + (u32)brow * PITCH;
        #pragma unroll
        for (int jj = 0; jj < 2; ++jj) {
            cp16(sB + OF_BH + (bp0 + jj) * 16, gwh + k0 + (bp0 + jj) * 16);
            cp16(sB + OF_BL + (bp0 + jj) * 16, gwl + k0 + (bp0 + jj) * 16);
        }
        CP_COMMIT();
        #pragma unroll
        for (int j = 0; j < 8; ++j) {
            const u32 sA = sb + sAoff + (u32)j * (8 * PITCH);
            sts32(sA,         qh[j]);
            sts32(sA + OF_AL, ql[j]);
        }
        CP_WAIT0();
    }
    __syncthreads();

    // ---------- main loop ----------
    for (int it = 0; it < NIT; ++it) {
        const int buf = it & 1;
        const int ns  = min(2, ucnt - 2 * it);
        const int nsn = (it + 1 < NIT) ? min(2, ucnt - 2 * (it + 1)) : 0;
        const u32 bb  = sb + (u32)buf * BUFSZ;
        const u32 nb  = sb + (u32)(buf ^ 1) * BUFSZ;
        const bool aload = (c16 < nsn * 8);

        // prefetch next chunk: LDG A (+quantize immediately) + cp.async B
        if (nsn > 0) {
            const int k0 = (ubeg + 2 * (it + 1)) * 32;
            if (aload) {
                const float* ap = abase + k0 + c16 * 4;
                #pragma unroll
                for (int j = 0; j < 8; ++j) {
                    float4 v = *reinterpret_cast<const float4*>(
                        ap + (size_t)(arow0 + 8 * j) * V_SZ);
                    quant4(v, qh[j], ql[j]);
                }
            }
            const u32 sB = nb + (u32)brow * PITCH;
            #pragma unroll
            for (int jj = 0; jj < 2; ++jj) {
                const int p = bp0 + jj;
                if (p < 2 * nsn) {
                    cp16(sB + OF_BH + p * 16, gwh + k0 + p * 16);
                    cp16(sB + OF_BL + p * 16, gwl + k0 + p * 16);
                }
            }
            CP_COMMIT();
        }

        // MMA on current buffer
        for (int s = 0; s < ns; ++s) {
            const u32 so = (u32)s * 32;
            u32 ah[2][4], al[2][4];
            #pragma unroll
            for (int mt = 0; mt < 2; ++mt) {
                u32 a = bb + aLB + (u32)mt * (16 * PITCH) + so;
                ldm4(a,         ah[mt]);
                ldm4(a + OF_AL, al[mt]);
            }
            #pragma unroll
            for (int q = 0; q < 2; ++q) {
                u32 bh[4], bl[4];
                u32 a = bb + bLB + (u32)q * (16 * PITCH) + so;
                ldm4(a + OF_BH, bh);
                ldm4(a + OF_BL, bl);
                #pragma unroll
                for (int mt = 0; mt < 2; ++mt)
                    #pragma unroll
                    for (int h = 0; h < 2; ++h) {
                        imma(acc1[mt][q * 2 + h], ah[mt], &bh[2 * h]);
                        imma(acc2[mt][q * 2 + h], ah[mt], &bl[2 * h]);
                        imma(acc2[mt][q * 2 + h], al[mt], &bh[2 * h]);
                    }
            }
        }

        // store next chunk's A (already quantized)
        if (nsn > 0 && aload) {
            #pragma unroll
            for (int j = 0; j < 8; ++j) {
                const u32 sA = nb + sAoff + (u32)j * (8 * PITCH);
                sts32(sA,         qh[j]);
                sts32(sA + OF_AL, ql[j]);
            }
        }
        CP_WAIT0();
        __syncthreads();
    }

    // ---- epilogue: combine s32 accs -> fp32 partials ----
    const int r4 = lane >> 2, c4 = lane & 3;
    const int col0 = wn * 32;
    #pragma unroll
    for (int mt = 0; mt < 2; ++mt) {
        const size_t rg = (size_t)row0 + wm * 32 + mt * 16 + r4;
        float* base = &g_part[((size_t)ks * M_ALL + rg) * D_SZ + col0];
        #pragma unroll
        for (int nt = 0; nt < 4; ++nt) {
            float v0 = fmaf((float)acc1[mt][nt][0], K1SC, (float)acc2[mt][nt][0] * K2SC);
            float v1 = fmaf((float)acc1[mt][nt][1], K1SC, (float)acc2[mt][nt][1] * K2SC);
            float v2 = fmaf((float)acc1[mt][nt][2], K1SC, (float)acc2[mt][nt][2] * K2SC);
            float v3 = fmaf((float)acc1[mt][nt][3], K1SC, (float)acc2[mt][nt][3] * K2SC);
            *(float2*)(base + nt * 8 + c4 * 2)                    = make_float2(v0, v1);
            *(float2*)(base + 8 * (size_t)D_SZ + nt * 8 + c4 * 2) = make_float2(v2, v3);
        }
    }
}

// ---- K2: reduce k-slices + bias -> g_sup --------------------------------------
__global__ void reduce_kernel(const float* __restrict__ bias) {
    int idx = blockIdx.x * 256 + threadIdx.x;       // covers M_ALL*D exactly
    float s = bias[idx & 63];
    #pragma unroll
    for (int ks = 0; ks < KSPLIT; ++ks)
        s += g_part[(size_t)ks * M_ALL * D_SZ + idx];
    g_sup[idx] = s;
}

// ---- K3: warp-per-episode sims/softmax/preds/argmax/CE ------------------------
__global__ void sim_kernel(const float* __restrict__ onehot,
                           const int* __restrict__ tgty)
{
    const int b    = blockIdx.x;                    // 256 blocks, 32 threads
    const int lane = threadIdx.x;
    const unsigned FULL = 0xFFFFFFFFu;

    const float4* t4 = (const float4*)&g_sup[(size_t)(M_SUP + b) * D_SZ];
    float sim = -3.0e38f;
    if (lane < S_SZ) {
        const float4* s4 = (const float4*)&g_sup[(size_t)(b * S_SZ + lane) * D_SZ];
        float d0 = 0.f, d1 = 0.f, d2 = 0.f, d3 = 0.f;
        float m0 = 0.f, m1 = 0.f, m2 = 0.f, m3 = 0.f;
        #pragma unroll
        for (int i = 0; i < 16; ++i) {
            float4 s = s4[i], t = t4[i];
            d0 += s.x * t.x; d1 += s.y * t.y; d2 += s.z * t.z; d3 += s.w * t.w;
            m0 += s.x * s.x; m1 += s.y * s.y; m2 += s.z * s.z; m3 += s.w * s.w;
        }
        float dot = (d0 + d1) + (d2 + d3);
        float mag = (m0 + m1) + (m2 + m3);
        sim = dot * rsqrtf(fmaxf(mag, 1e-10f));
    }
    float m = sim;
    #pragma unroll
    for (int o = 16; o; o >>= 1) m = fmaxf(m, __shfl_xor_sync(FULL, m, o));
    float e = (lane < S_SZ) ? expf(sim - m) : 0.f;
    float sum = e;
    #pragma unroll
    for (int o = 16; o; o >>= 1) sum += __shfl_xor_sync(FULL, sum, o);
    float attn = e / sum;

    float p = 0.f;
    #pragma unroll
    for (int s = 0; s < S_SZ; ++s) {
        float a = __shfl_sync(FULL, attn, s);
        if (lane < C_SZ) p += a * onehot[((size_t)b * S_SZ + s) * C_SZ + lane];
    }

    float bv = (lane < C_SZ) ? p : -3.0e38f;
    int   bi = (lane < C_SZ) ? lane : 999;
    #pragma unroll
    for (int o = 16; o; o >>= 1) {
        float ov = __shfl_xor_sync(FULL, bv, o);
        int   oi = __shfl_xor_sync(FULL, bi, o);
        if (ov > bv || (ov == bv && oi < bi)) { bv = ov; bi = oi; }
    }
    float pm = (lane < C_SZ) ? p : -3.0e38f;
    #pragma unroll
    for (int o = 16; o; o >>= 1) pm = fmaxf(pm, __shfl_xor_sync(FULL, pm, o));
    float ee = (lane < C_SZ) ? expf(p - pm) : 0.f;
    float lse = ee;
    #pragma unroll
    for (int o = 16; o; o >>= 1) lse += __shfl_xor_sync(FULL, lse, o);

    int y = tgty[b];
    float py = __shfl_sync(FULL, p, y);
    if (lane == 0) {
        g_pb[b]        = (bi == y) ? 1.f : 0.f;
        g_pb[B_SZ + b] = -(py - pm - logf(lse));
    }
}

// ---- K4: deterministic final reduction -> d_out -------------------------------
__global__ void finalize_kernel(float* __restrict__ out) {
    __shared__ float sc[B_SZ], sl[B_SZ];
    int t = threadIdx.x;
    sc[t] = g_pb[t];
    sl[t] = g_pb[B_SZ + t];
    __syncthreads();
    for (int off = 128; off > 0; off >>= 1) {
        if (t < off) { sc[t] += sc[t + off]; sl[t] += sl[t + off]; }
        __syncthreads();
    }
    if (t == 0) {
        out[0] = sc[0] * (1.f / (float)B_SZ);
        out[1] = sl[0] * (1.f / (float)B_SZ);
    }
}

// ---------------------------------------------------------------------------
extern "C" void kernel_launch(void* const* d_in, const int* in_sizes, int n_in,
                              void* d_out, int out_size)
{
    const float* img    = (const float*)d_in[0];   // [256,20,20000]
    const float* onehot = (const float*)d_in[1];   // [256,20,20]
    const float* tgtim  = (const float*)d_in[2];   // [256,20000]
    const int*   tgty   = (const int*)  d_in[3];   // [256]
    const float* W      = (const float*)d_in[4];   // [64,20000]
    const float* bias   = (const float*)d_in[5];   // [64]
    float* out = (float*)d_out;                    // [2]

    cudaFuncSetAttribute(gemm_kernel,
                         cudaFuncAttributeMaxDynamicSharedMemorySize, SMEM_TOTAL);

    prep_w_kernel<<<(D_SZ * V_SZ / 4) / 256, 256>>>(W);
    gemm_kernel<<<dim3(M_ALL / 64, KSPLIT), 128, SMEM_TOTAL>>>(img, tgtim);
    reduce_kernel<<<(M_ALL * D_SZ) / 256, 256>>>(bias);
    sim_kernel<<<B_SZ, 32>>>(onehot, tgty);
    finalize_kernel<<<1, B_SZ>>>(out);
}

// round 8
// speedup vs baseline: 1.2430x; 1.2430x over previous
#include <cuda_runtime.h>
#include <cuda_bf16.h>
#include <cstdint>

// ---------------------------------------------------------------------------
// MatchingNetwork — Round 8: split-bf16 HMMA (R3 numerics, rt~8 verified)
// on the R7 pipeline: M-tile 64, 128 thr, double buffer, coalesced A,
// register-staged quantize. 3-term: Ah*Bh + Ah*Bl + Al*Bh into one fp32 acc.
// ---------------------------------------------------------------------------

#define B_SZ   256
#define S_SZ   20
#define V_SZ   20000
#define C_SZ   20
#define D_SZ   64
#define M_SUP  (B_SZ * S_SZ)      // 5120
#define M_ALL  (M_SUP + B_SZ)     // 5376
#define KSPLIT 7
#define NIT    45                 // 64-elem chunks per k-slice (4 k16 steps)

#define PITCH  144u               // 64 bf16 = 128B + 16B pad (conflict-free)
#define OF_AL  9216u              // 64*144
#define OF_BH  18432u
#define OF_BL  27648u
#define BUFSZ  36864u
#define SMEM_TOTAL 73728

typedef uint32_t u32;

// ---- device scratch ---------------------------------------------------------
__device__ float         g_part[(size_t)KSPLIT * M_ALL * D_SZ];
__device__ float         g_sup[(size_t)M_ALL * D_SZ];
__device__ __nv_bfloat16 g_Whi[(size_t)D_SZ * V_SZ];
__device__ __nv_bfloat16 g_Wlo[(size_t)D_SZ * V_SZ];
__device__ float         g_pb[2 * B_SZ];

// ---- PTX helpers ------------------------------------------------------------
__device__ __forceinline__ u32 smem_u32(const void* p) {
    u32 a;
    asm("{ .reg .u64 t; cvta.to.shared.u64 t, %1; cvt.u32.u64 %0, t; }"
        : "=r"(a) : "l"(p));
    return a;
}
__device__ __forceinline__ void sts64(u32 a, u32 v0, u32 v1) {
    asm volatile("st.shared.v2.b32 [%0], {%1, %2};" :: "r"(a), "r"(v0), "r"(v1));
}
__device__ __forceinline__ void cp16(u32 s, const void* g) {
    asm volatile("cp.async.cg.shared.global [%0], [%1], 16;" :: "r"(s), "l"(g));
}
#define CP_COMMIT() asm volatile("cp.async.commit_group;" ::: "memory")
#define CP_WAIT0()  asm volatile("cp.async.wait_group 0;" ::: "memory")

__device__ __forceinline__ void ldm4(u32 a, u32 r[4]) {
    asm volatile("ldmatrix.sync.aligned.m8n8.x4.shared.b16 {%0,%1,%2,%3}, [%4];"
        : "=r"(r[0]), "=r"(r[1]), "=r"(r[2]), "=r"(r[3]) : "r"(a));
}
__device__ __forceinline__ void mma16816(float c[4], const u32 a[4],
                                         const u32* b) {
    asm volatile("mma.sync.aligned.m16n8k16.row.col.f32.bf16.bf16.f32 "
        "{%0,%1,%2,%3}, {%4,%5,%6,%7}, {%8,%9}, {%0,%1,%2,%3};"
        : "+f"(c[0]), "+f"(c[1]), "+f"(c[2]), "+f"(c[3])
        : "r"(a[0]), "r"(a[1]), "r"(a[2]), "r"(a[3]), "r"(b[0]), "r"(b[1]));
}
__device__ __forceinline__ u32 cvt2bf(float lo, float hi) {
    u32 r;   // low half <- lo, high half <- hi
    asm("cvt.rn.bf16x2.f32 %0, %1, %2;" : "=r"(r) : "f"(hi), "f"(lo));
    return r;
}
// float4 -> bf16 hi pair (h0,h1) and lo-residual pair (l0,l1)
__device__ __forceinline__ void split4(float4 v, u32& h0, u32& h1,
                                       u32& l0, u32& l1) {
    h0 = cvt2bf(v.x, v.y);
    h1 = cvt2bf(v.z, v.w);
    float r0 = v.x - __uint_as_float(h0 << 16);
    float r1 = v.y - __uint_as_float(h0 & 0xFFFF0000u);
    float r2 = v.z - __uint_as_float(h1 << 16);
    float r3 = v.w - __uint_as_float(h1 & 0xFFFF0000u);
    l0 = cvt2bf(r0, r1);
    l1 = cvt2bf(r2, r3);
}

// ---- K0: split W into bf16 hi/lo ---------------------------------------------
__global__ void prep_w_kernel(const float* __restrict__ W) {
    int idx = blockIdx.x * 256 + threadIdx.x;          // covers D*V exactly
    float x  = W[idx];
    __nv_bfloat16 h = __float2bfloat16_rn(x);
    g_Whi[idx] = h;
    g_Wlo[idx] = __float2bfloat16_rn(x - __bfloat162float(h));
}

// ---- K1: split-bf16 HMMA GEMM, M-tile 64, double-buffered ----------------------
// grid = (84 m-tiles, 7 k-slices), 4 warps in 2x2, warp tile m32 x n32
__global__ __launch_bounds__(128) void gemm_kernel(
    const float* __restrict__ img, const float* __restrict__ tgtim)
{
    extern __shared__ char smem[];
    const u32 sb = smem_u32(smem);
    const int tid  = threadIdx.x;
    const int w    = tid >> 5;
    const int lane = tid & 31;
    const int wm   = w >> 1;             // m half
    const int wn   = w & 1;              // n half
    const int row0 = blockIdx.x * 64;
    const int ks   = blockIdx.y;

    // k-slice in k16 steps: 1250 -> 4x179 + 3x178
    const int ubeg = ks * 178 + (ks < 4 ? ks : 4);
    const int ucnt = 178 + (ks < 4 ? 1 : 0);

    const float* abase = (blockIdx.x < 80)
        ? img   + (size_t)row0 * V_SZ
        : tgtim + (size_t)(row0 - M_SUP) * V_SZ;

    // A fill (coalesced): 16 lanes cover one row's 64 floats; 8 rows/pass, 8 passes
    const int arow0 = tid >> 4;          // 0..7
    const int c16   = tid & 15;          // float4 index within 64-elem row chunk
    // B fill: 2 threads per row (64 d-rows), 4 x 16B pieces per array each
    const int brow = tid >> 1, bhalf = tid & 1;
    const char* gwh = (const char*)(g_Whi + (size_t)brow * V_SZ);
    const char* gwl = (const char*)(g_Wlo + (size_t)brow * V_SZ);

    // ldmatrix lane bases (layouts verified in R3)
    const u32 aLB = (u32)(wm * 32 + (lane & 15)) * PITCH + (u32)((lane >> 4) * 16);
    const u32 bLB = (u32)(wn * 32 + (lane & 7) + ((lane >> 4) & 1) * 8) * PITCH
                  + (u32)(((lane >> 3) & 1) * 16);

    float acc[2][4][4];
    #pragma unroll
    for (int mt = 0; mt < 2; ++mt)
        #pragma unroll
        for (int nt = 0; nt < 4; ++nt)
            #pragma unroll
            for (int i = 0; i < 4; ++i) acc[mt][nt][i] = 0.f;

    u32 h0s[8], h1s[8], l0s[8], l1s[8];          // 32-reg staging
    const u32 sAoff = (u32)arow0 * PITCH + (u32)c16 * 8;

    // ---------- prologue: fill buffer 0 (chunk 0, ns=4) ----------
    {
        const int k0 = ubeg * 16;
        const float* ap = abase + k0 + c16 * 4;
        #pragma unroll
        for (int j = 0; j < 8; ++j) {
            float4 v = *reinterpret_cast<const float4*>(ap + (size_t)(arow0 + 8 * j) * V_SZ);
            split4(v, h0s[j], h1s[j], l0s[j], l1s[j]);
        }
        const u32 sB = sb + (u32)brow * PITCH + (u32)bhalf * 64;
        const char* gh = gwh + (size_t)k0 * 2 + bhalf * 64;
        const char* gl = gwl + (size_t)k0 * 2 + bhalf * 64;
        #pragma unroll
        for (int p = 0; p < 4; ++p) {
            cp16(sB + OF_BH + p * 16, gh + p * 16);
            cp16(sB + OF_BL + p * 16, gl + p * 16);
        }
        CP_COMMIT();
        #pragma unroll
        for (int j = 0; j < 8; ++j) {
            const u32 sA = sb + sAoff + (u32)j * (8 * PITCH);
            sts64(sA,         h0s[j], h1s[j]);
            sts64(sA + OF_AL, l0s[j], l1s[j]);
        }
        CP_WAIT0();
    }
    __syncthreads();

    // ---------- main loop ----------
    for (int it = 0; it < NIT; ++it) {
        const int buf = it & 1;
        const int ns  = min(4, ucnt - 4 * it);
        const int nsn = (it + 1 < NIT) ? min(4, ucnt - 4 * (it + 1)) : 0;
        const u32 bb  = sb + (u32)buf * BUFSZ;
        const u32 nb  = sb + (u32)(buf ^ 1) * BUFSZ;
        const bool aload = (c16 < nsn * 4);

        // prefetch next chunk: LDG A (+split immediately) + cp.async B
        if (nsn > 0) {
            const int k0 = (ubeg + 4 * (it + 1)) * 16;
            if (aload) {
                const float* ap = abase + k0 + c16 * 4;
                #pragma unroll
                for (int j = 0; j < 8; ++j) {
                    float4 v = *reinterpret_cast<const float4*>(
                        ap + (size_t)(arow0 + 8 * j) * V_SZ);
                    split4(v, h0s[j], h1s[j], l0s[j], l1s[j]);
                }
            }
            const u32 sB = nb + (u32)brow * PITCH + (u32)bhalf * 64;
            const char* gh = gwh + (size_t)k0 * 2 + bhalf * 64;
            const char* gl = gwl + (size_t)k0 * 2 + bhalf * 64;
            #pragma unroll
            for (int p = 0; p < 4; ++p) {
                if (bhalf * 4 + p < nsn * 2) {
                    cp16(sB + OF_BH + p * 16, gh + p * 16);
                    cp16(sB + OF_BL + p * 16, gl + p * 16);
                }
            }
            CP_COMMIT();
        }

        // MMA on current buffer
        for (int s = 0; s < ns; ++s) {
            const u32 so = (u32)s * 32;
            u32 ah[2][4], al[2][4];
            #pragma unroll
            for (int mt = 0; mt < 2; ++mt) {
                u32 a = bb + aLB + (u32)mt * (16 * PITCH) + so;
                ldm4(a,         ah[mt]);
                ldm4(a + OF_AL, al[mt]);
            }
            #pragma unroll
            for (int q = 0; q < 2; ++q) {
                u32 bh[4], bl[4];
                u32 a = bb + bLB + (u32)q * (16 * PITCH) + so;
                ldm4(a + OF_BH, bh);
                ldm4(a + OF_BL, bl);
                #pragma unroll
                for (int mt = 0; mt < 2; ++mt)
                    #pragma unroll
                    for (int h = 0; h < 2; ++h) {
                        float* cc = acc[mt][q * 2 + h];
                        mma16816(cc, ah[mt], &bh[2 * h]);
                        mma16816(cc, ah[mt], &bl[2 * h]);
                        mma16816(cc, al[mt], &bh[2 * h]);
                    }
            }
        }

        // store next chunk's A (already split)
        if (nsn > 0 && aload) {
            #pragma unroll
            for (int j = 0; j < 8; ++j) {
                const u32 sA = nb + sAoff + (u32)j * (8 * PITCH);
                sts64(sA,         h0s[j], h1s[j]);
                sts64(sA + OF_AL, l0s[j], l1s[j]);
            }
        }
        CP_WAIT0();
        __syncthreads();
    }

    // ---- epilogue: store fp32 partials ----
    const int r4 = lane >> 2, c4 = lane & 3;
    const int col0 = wn * 32;
    #pragma unroll
    for (int mt = 0; mt < 2; ++mt) {
        const size_t rg = (size_t)row0 + wm * 32 + mt * 16 + r4;
        float* base = &g_part[((size_t)ks * M_ALL + rg) * D_SZ + col0];
        #pragma unroll
        for (int nt = 0; nt < 4; ++nt) {
            *(float2*)(base + nt * 8 + c4 * 2) =
                make_float2(acc[mt][nt][0], acc[mt][nt][1]);
            *(float2*)(base + 8 * (size_t)D_SZ + nt * 8 + c4 * 2) =
                make_float2(acc[mt][nt][2], acc[mt][nt][3]);
        }
    }
}

// ---- K2: reduce k-slices + bias -> g_sup --------------------------------------
__global__ void reduce_kernel(const float* __restrict__ bias) {
    int idx = blockIdx.x * 256 + threadIdx.x;       // covers M_ALL*D exactly
    float s = bias[idx & 63];
    #pragma unroll
    for (int ks = 0; ks < KSPLIT; ++ks)
        s += g_part[(size_t)ks * M_ALL * D_SZ + idx];
    g_sup[idx] = s;
}

// ---- K3: warp-per-episode sims/softmax/preds/argmax/CE ------------------------
__global__ void sim_kernel(const float* __restrict__ onehot,
                           const int* __restrict__ tgty)
{
    const int b    = blockIdx.x;                    // 256 blocks, 32 threads
    const int lane = threadIdx.x;
    const unsigned FULL = 0xFFFFFFFFu;

    const float4* t4 = (const float4*)&g_sup[(size_t)(M_SUP + b) * D_SZ];
    float sim = -3.0e38f;
    if (lane < S_SZ) {
        const float4* s4 = (const float4*)&g_sup[(size_t)(b * S_SZ + lane) * D_SZ];
        float d0 = 0.f, d1 = 0.f, d2 = 0.f, d3 = 0.f;
        float m0 = 0.f, m1 = 0.f, m2 = 0.f, m3 = 0.f;
        #pragma unroll
        for (int i = 0; i < 16; ++i) {
            float4 s = s4[i], t = t4[i];
            d0 += s.x * t.x; d1 += s.y * t.y; d2 += s.z * t.z; d3 += s.w * t.w;
            m0 += s.x * s.x; m1 += s.y * s.y; m2 += s.z * s.z; m3 += s.w * s.w;
        }
        float dot = (d0 + d1) + (d2 + d3);
        float mag = (m0 + m1) + (m2 + m3);
        sim = dot * rsqrtf(fmaxf(mag, 1e-10f));
    }
    float m = sim;
    #pragma unroll
    for (int o = 16; o; o >>= 1) m = fmaxf(m, __shfl_xor_sync(FULL, m, o));
    float e = (lane < S_SZ) ? expf(sim - m) : 0.f;
    float sum = e;
    #pragma unroll
    for (int o = 16; o; o >>= 1) sum += __shfl_xor_sync(FULL, sum, o);
    float attn = e / sum;

    float p = 0.f;
    #pragma unroll
    for (int s = 0; s < S_SZ; ++s) {
        float a = __shfl_sync(FULL, attn, s);
        if (lane < C_SZ) p += a * onehot[((size_t)b * S_SZ + s) * C_SZ + lane];
    }

    float bv = (lane < C_SZ) ? p : -3.0e38f;
    int   bi = (lane < C_SZ) ? lane : 999;
    #pragma unroll
    for (int o = 16; o; o >>= 1) {
        float ov = __shfl_xor_sync(FULL, bv, o);
        int   oi = __shfl_xor_sync(FULL, bi, o);
        if (ov > bv || (ov == bv && oi < bi)) { bv = ov; bi = oi; }
    }
    float pm = (lane < C_SZ) ? p : -3.0e38f;
    #pragma unroll
    for (int o = 16; o; o >>= 1) pm = fmaxf(pm, __shfl_xor_sync(FULL, pm, o));
    float ee = (lane < C_SZ) ? expf(p - pm) : 0.f;
    float lse = ee;
    #pragma unroll
    for (int o = 16; o; o >>= 1) lse += __shfl_xor_sync(FULL, lse, o);

    int y = tgty[b];
    float py = __shfl_sync(FULL, p, y);
    if (lane == 0) {
        g_pb[b]        = (bi == y) ? 1.f : 0.f;
        g_pb[B_SZ + b] = -(py - pm - logf(lse));
    }
}

// ---- K4: deterministic final reduction -> d_out -------------------------------
__global__ void finalize_kernel(float* __restrict__ out) {
    __shared__ float sc[B_SZ], sl[B_SZ];
    int t = threadIdx.x;
    sc[t] = g_pb[t];
    sl[t] = g_pb[B_SZ + t];
    __syncthreads();
    for (int off = 128; off > 0; off >>= 1) {
        if (t < off) { sc[t] += sc[t + off]; sl[t] += sl[t + off]; }
        __syncthreads();
    }
    if (t == 0) {
        out[0] = sc[0] * (1.f / (float)B_SZ);
        out[1] = sl[0] * (1.f / (float)B_SZ);
    }
}

// ---------------------------------------------------------------------------
extern "C" void kernel_launch(void* const* d_in, const int* in_sizes, int n_in,
                              void* d_out, int out_size)
{
    const float* img    = (const float*)d_in[0];   // [256,20,20000]
    const float* onehot = (const float*)d_in[1];   // [256,20,20]
    const float* tgtim  = (const float*)d_in[2];   // [256,20000]
    const int*   tgty   = (const int*)  d_in[3];   // [256]
    const float* W      = (const float*)d_in[4];   // [64,20000]
    const float* bias   = (const float*)d_in[5];   // [64]
    float* out = (float*)d_out;                    // [2]

    cudaFuncSetAttribute(gemm_kernel,
                         cudaFuncAttributeMaxDynamicSharedMemorySize, SMEM_TOTAL);

    prep_w_kernel<<<(D_SZ * V_SZ) / 256, 256>>>(W);
    gemm_kernel<<<dim3(M_ALL / 64, KSPLIT), 128, SMEM_TOTAL>>>(img, tgtim);
    reduce_kernel<<<(M_ALL * D_SZ) / 256, 256>>>(bias);
    sim_kernel<<<B_SZ, 32>>>(onehot, tgty);
    finalize_kernel<<<1, B_SZ>>>(out);
}